// round 6
// baseline (speedup 1.0000x reference)
#include <cuda_runtime.h>
#include <cuda_bf16.h>
#include <cstdint>
#include <cstddef>

#define BB 2
#define NN 256
#define DD 256

// ---------------------------------------------------------------------------
// PTX helpers (sm_80+ paths only; compile clean for plain sm_100)
// ---------------------------------------------------------------------------
__device__ __forceinline__ uint32_t smem_u32(const void* p) {
    uint32_t a;
    asm("{ .reg .u64 t; cvta.to.shared.u64 t, %1; cvt.u32.u64 %0, t; }" : "=r"(a) : "l"(p));
    return a;
}
__device__ __forceinline__ void ldsm_x4(uint32_t* r, uint32_t addr) {
    asm volatile("ldmatrix.sync.aligned.m8n8.x4.shared.b16 {%0,%1,%2,%3}, [%4];"
                 : "=r"(r[0]), "=r"(r[1]), "=r"(r[2]), "=r"(r[3]) : "r"(addr));
}
__device__ __forceinline__ void mma_bf16(float* c, const uint32_t* a, const uint32_t* b) {
    asm volatile(
        "mma.sync.aligned.m16n8k16.row.col.f32.bf16.bf16.f32 "
        "{%0,%1,%2,%3}, {%4,%5,%6,%7}, {%8,%9}, {%0,%1,%2,%3};"
        : "+f"(c[0]), "+f"(c[1]), "+f"(c[2]), "+f"(c[3])
        : "r"(a[0]), "r"(a[1]), "r"(a[2]), "r"(a[3]), "r"(b[0]), "r"(b[1]));
}
__device__ __forceinline__ void cp16(uint32_t saddr, const void* gptr) {
    asm volatile("cp.async.cg.shared.global [%0], [%1], 16;" :: "r"(saddr), "l"(gptr));
}
__device__ __forceinline__ void cp_commit() { asm volatile("cp.async.commit_group;"); }
__device__ __forceinline__ void cp_wait_all() { asm volatile("cp.async.wait_group 0;"); }

// ---------------------------------------------------------------------------
// Device scratch
// ---------------------------------------------------------------------------
__device__ float g_xi[BB * NN * DD];
__device__ float g_xj[BB * NN * DD];
// w_alpha split bf16 hi/lo, kstep-chunked: [ks][n] -> 64B = [16 hi][16 lo]
__device__ uint4 g_wB[16 * 256 * 4];        // 262144 bytes

// ---------------------------------------------------------------------------
// SMEM layout (bytes). Per-CTA total 108544 -> 2 CTAs/SM.
//   sA: 64 rows x 512B, XOR-swizzled 16B units; hi at 0, lo at +32768
//   sB: 2 bufs x (256 n x 80B rows: [32B hi][32B lo][16B pad])
//   red (2KB) aliases sB buf0 (only used after all MMA done)
// ---------------------------------------------------------------------------
#define SM_AHI 0
#define SM_ALO 32768
#define SM_B   65536
#define SB_BUF 20480
#define SM_XI  106496
#define SM_ADJ 107520
#define SM_RED SM_B
#define SMEM_BYTES 108544

// ---------------------------------------------------------------------------
// Kernel 1: xi = x @ w_vi, xj = x @ w_vj  (row-tiled: 128 CTAs x 4 rows)
// ---------------------------------------------------------------------------
__global__ void __launch_bounds__(256) proj_kernel(const float* __restrict__ x,
                                                   const float* __restrict__ w_vi,
                                                   const float* __restrict__ w_vj)
{
    __shared__ float sX[4][DD];
    const int r0 = blockIdx.x * 4;
    const int tid = threadIdx.x;
#pragma unroll
    for (int i = 0; i < 4; i++) sX[i][tid] = x[(r0 + i) * DD + tid];
    __syncthreads();
    float ai[4] = {0.f, 0.f, 0.f, 0.f}, aj[4] = {0.f, 0.f, 0.f, 0.f};
#pragma unroll 4
    for (int d = 0; d < DD; d++) {
        const float wv = w_vi[d * DD + tid];
        const float wj = w_vj[d * DD + tid];
#pragma unroll
        for (int r = 0; r < 4; r++) {
            const float xr = sX[r][d];
            ai[r] = fmaf(xr, wv, ai[r]);
            aj[r] = fmaf(xr, wj, aj[r]);
        }
    }
#pragma unroll
    for (int r = 0; r < 4; r++) {
        g_xi[(r0 + r) * DD + tid] = ai[r];
        g_xj[(r0 + r) * DD + tid] = aj[r];
    }
}

// ---------------------------------------------------------------------------
// Kernel 2: split w_alpha into bf16 hi/lo in kstep-chunked layout
// ---------------------------------------------------------------------------
__global__ void __launch_bounds__(256) wconv_kernel(const float* __restrict__ w_alpha)
{
    const int idx = blockIdx.x * 256 + threadIdx.x;   // d*256 + n
    const int d = idx >> 8;
    const int n = idx & 255;
    const float v = w_alpha[idx];
    const __nv_bfloat16 hi = __float2bfloat16(v);
    const __nv_bfloat16 lo = __float2bfloat16(v - __bfloat162float(hi));
    __nv_bfloat16* wb = (__nv_bfloat16*)g_wB;
    const int base = (d >> 4) * 8192 + n * 32 + (d & 15);
    wb[base]      = hi;
    wb[base + 16] = lo;
}

// ---------------------------------------------------------------------------
// Main kernel: CTA per (b,i); 4 j-tiles of 64 rows; bf16x3 on mma.sync
// ---------------------------------------------------------------------------
__device__ __forceinline__ void build_A(char* smem, uint32_t sb,
                                        const float* __restrict__ alpha_base,
                                        const float* __restrict__ xjB,
                                        const float* __restrict__ biasB,
                                        int j0, int tid, float& ah0, float& ah1)
{
    const float* sXi  = (const float*)(smem + SM_XI);
    const float* sAdj = (const float*)(smem + SM_ADJ);
    const int d0  = (tid & 127) * 2;
    const int par = tid >> 7;
    const float xi0 = sXi[d0], xi1 = sXi[d0 + 1];
    const uint32_t u   = (uint32_t)(tid & 127) >> 2;           // 16B unit of this d-pair
    const uint32_t inB = (uint32_t)((tid & 127) & 3) * 4;      // byte within unit
#pragma unroll 4
    for (int jj = par; jj < 64; jj += 2) {
        const size_t off = (size_t)(j0 + jj) * DD + d0;
        const float2 av = *(const float2*)(alpha_base + off);
        const float2 xv = *(const float2*)(xjB + off);
        const float2 bv = *(const float2*)(biasB + off);
        const float h0 = fmaxf(av.x + xv.x + bv.x + xi0, 0.f);
        const float h1 = fmaxf(av.y + xv.y + bv.y + xi1, 0.f);
        const float aw = sAdj[j0 + jj];
        ah0 = fmaf(aw, h0, ah0);
        ah1 = fmaf(aw, h1, ah1);
        const __nv_bfloat16 hh0 = __float2bfloat16(h0);
        const __nv_bfloat16 hh1 = __float2bfloat16(h1);
        const __nv_bfloat16 hl0 = __float2bfloat16(h0 - __bfloat162float(hh0));
        const __nv_bfloat16 hl1 = __float2bfloat16(h1 - __bfloat162float(hh1));
        const uint32_t hp = ((uint32_t)__bfloat16_as_ushort(hh1) << 16) | __bfloat16_as_ushort(hh0);
        const uint32_t lp = ((uint32_t)__bfloat16_as_ushort(hl1) << 16) | __bfloat16_as_ushort(hl0);
        const uint32_t addr = (uint32_t)jj * 512u + ((u ^ (uint32_t)(jj & 7)) << 4) + inB;
        *(uint32_t*)(smem + SM_AHI + addr) = hp;
        *(uint32_t*)(smem + SM_ALO + addr) = lp;
    }
}

__device__ __forceinline__ void stage_B_async(uint32_t sb, int ks, int buf, int tid)
{
    const char* g = (const char*)g_wB + (size_t)ks * 16384 + (size_t)tid * 64;
    const uint32_t s = sb + SM_B + (uint32_t)buf * SB_BUF + (uint32_t)tid * 80;
    cp16(s,      g);
    cp16(s + 16, g + 16);
    cp16(s + 32, g + 32);
    cp16(s + 48, g + 48);
    cp_commit();
}

__global__ void __launch_bounds__(256, 2) main_kernel(
    const float* __restrict__ alpha,
    const float* __restrict__ adj,
    const float* __restrict__ bias_h,
    const float* __restrict__ w_node,
    float* __restrict__ out_x,
    float* __restrict__ out_alpha)
{
    extern __shared__ char smem[];
    const uint32_t sb = smem_u32(smem);
    const int tid  = threadIdx.x;
    const int wid  = tid >> 5;
    const int lane = tid & 31;
    const int rg = wid & 1;         // 32-row group
    const int cg = wid >> 1;        // 64-col group
    const size_t bi = blockIdx.x;
    const int b = (int)(bi >> 8);

    ((float*)(smem + SM_XI))[tid]  = g_xi[bi * DD + tid];
    ((float*)(smem + SM_ADJ))[tid] = adj[bi * NN + tid];
    __syncthreads();

    const float* alpha_base = alpha + bi * (size_t)NN * DD;
    const float* xjB = g_xj + (size_t)b * NN * DD;

    // A ldsm addressing: row = rg*32 + (lane&15) (+16 for mb=1); chunk = ks*2 + (lane>>4)
    const int rowA = rg * 32 + (lane & 15);
    const uint32_t r7 = (uint32_t)(rowA & 7);
    const uint32_t aBase0 = sb + SM_AHI + (uint32_t)rowA * 512u;
    const uint32_t hilo = (uint32_t)(lane >> 4);
    // B ldsm addressing (x4 covers nb pair): n = cg*64 + nbp*16 + (lane&7) + ((lane&16)>>1)
    const uint32_t nrow = (uint32_t)(cg * 64 + (lane & 7) + ((lane & 16) >> 1));
    const uint32_t bBase = sb + SM_B + nrow * 80u + (uint32_t)((lane >> 3) & 1) * 16u;

    float ah0 = 0.f, ah1 = 0.f;
    float acc[2][8][4];

    // prologue: stage B ks0 for tile 0, build A tile 0
    stage_B_async(sb, 0, 0, tid);
    build_A(smem, sb, alpha_base, xjB, bias_h, 0, tid, ah0, ah1);
    cp_wait_all();
    __syncthreads();

#pragma unroll 1
    for (int t = 0; t < 4; t++) {
#pragma unroll
        for (int mb = 0; mb < 2; mb++)
#pragma unroll
            for (int nb = 0; nb < 8; nb++)
#pragma unroll
                for (int q = 0; q < 4; q++) acc[mb][nb][q] = 0.f;

#pragma unroll 1
        for (int ks = 0; ks < 16; ks++) {
            const int buf = ks & 1;
            if (ks < 15) stage_B_async(sb, ks + 1, buf ^ 1, tid);

            const uint32_t aOff = (((uint32_t)(ks * 2) + hilo) ^ r7) << 4;
            uint32_t Ah0[4], Ah1[4], Al0[4], Al1[4];
            ldsm_x4(Ah0, aBase0 + aOff);
            ldsm_x4(Ah1, aBase0 + 16 * 512 + aOff);
            ldsm_x4(Al0, aBase0 + (SM_ALO - SM_AHI) + aOff);
            ldsm_x4(Al1, aBase0 + (SM_ALO - SM_AHI) + 16 * 512 + aOff);

            const uint32_t bBuf = bBase + (uint32_t)buf * SB_BUF;
#pragma unroll
            for (int nbp = 0; nbp < 4; nbp++) {
                uint32_t Bh[4], Bl[4];
                ldsm_x4(Bh, bBuf + (uint32_t)nbp * 1280u);
                ldsm_x4(Bl, bBuf + (uint32_t)nbp * 1280u + 32u);
                const int nb = nbp * 2;
                mma_bf16(acc[0][nb],     Ah0, Bh);
                mma_bf16(acc[0][nb],     Al0, Bh);
                mma_bf16(acc[0][nb],     Ah0, Bl);
                mma_bf16(acc[1][nb],     Ah1, Bh);
                mma_bf16(acc[1][nb],     Al1, Bh);
                mma_bf16(acc[1][nb],     Ah1, Bl);
                mma_bf16(acc[0][nb + 1], Ah0, Bh + 2);
                mma_bf16(acc[0][nb + 1], Al0, Bh + 2);
                mma_bf16(acc[0][nb + 1], Ah0, Bl + 2);
                mma_bf16(acc[1][nb + 1], Ah1, Bh + 2);
                mma_bf16(acc[1][nb + 1], Al1, Bh + 2);
                mma_bf16(acc[1][nb + 1], Ah1, Bl + 2);
            }
            if (ks < 15) cp_wait_all();
            __syncthreads();
        }

        // stage B ks0 for next tile early (buf0 free: last read was ks14)
        if (t < 3) stage_B_async(sb, 0, 0, tid);

        // epilogue (register-only source)
        {
            const int j0 = t * 64;
            const int r0 = rg * 32 + (lane >> 2);
            const int c0 = cg * 64 + (lane & 3) * 2;
#pragma unroll
            for (int mb = 0; mb < 2; mb++) {
#pragma unroll
                for (int nb = 0; nb < 8; nb++) {
                    float* base = out_alpha + ((size_t)bi * NN + j0 + r0 + mb * 16) * DD + c0 + nb * 8;
                    float2 v0, v1;
                    v0.x = fmaxf(acc[mb][nb][0], 0.f);
                    v0.y = fmaxf(acc[mb][nb][1], 0.f);
                    v1.x = fmaxf(acc[mb][nb][2], 0.f);
                    v1.y = fmaxf(acc[mb][nb][3], 0.f);
                    *(float2*)base = v0;
                    *(float2*)(base + 8 * DD) = v1;
                }
            }
        }

        if (t < 3) {
            build_A(smem, sb, alpha_base, xjB, bias_h, (t + 1) * 64, tid, ah0, ah1);
            cp_wait_all();
            __syncthreads();
        }
    }

    // ---- AH reduce + new_x (red aliases sB buf0; safe after final ks15 sync) ----
    {
        float* red = (float*)(smem + SM_RED);
        const int d0  = (tid & 127) * 2;
        const int par = tid >> 7;
        red[par * 256 + d0]     = ah0;
        red[par * 256 + d0 + 1] = ah1;
    }
    __syncthreads();
    {
        const float* red = (const float*)(smem + SM_RED);
        float acc2 = 0.f;
#pragma unroll 8
        for (int d = 0; d < DD; d++)
            acc2 = fmaf(red[d] + red[256 + d], w_node[d * DD + tid], acc2);
        out_x[bi * DD + tid] = fmaxf(acc2, 0.f);
    }
}

// ---------------------------------------------------------------------------
// Launch. Inputs: x, alpha, adj, w_alpha, w_vi, w_vj, bias_h, w_node
// Output: new_x (131072 f32) then new_alpha (33554432 f32)
// ---------------------------------------------------------------------------
extern "C" void kernel_launch(void* const* d_in, const int* in_sizes, int n_in,
                              void* d_out, int out_size)
{
    const float* x       = (const float*)d_in[0];
    const float* alpha   = (const float*)d_in[1];
    const float* adj     = (const float*)d_in[2];
    const float* w_alpha = (const float*)d_in[3];
    const float* w_vi    = (const float*)d_in[4];
    const float* w_vj    = (const float*)d_in[5];
    const float* bias_h  = (const float*)d_in[6];
    const float* w_node  = (const float*)d_in[7];

    float* out       = (float*)d_out;
    float* out_x     = out;
    float* out_alpha = out + BB * NN * DD;

    cudaFuncSetAttribute(main_kernel, cudaFuncAttributeMaxDynamicSharedMemorySize, SMEM_BYTES);

    proj_kernel<<<128, 256>>>(x, w_vi, w_vj);
    wconv_kernel<<<256, 256>>>(w_alpha);
    main_kernel<<<BB * NN, 256, SMEM_BYTES>>>(alpha, adj, bias_h, w_node, out_x, out_alpha);
}